// round 3
// baseline (speedup 1.0000x reference)
#include <cuda_runtime.h>
#include <cuda_fp16.h>

#define N_USERS 100000
#define N_ITEMS 50000
#define N_ROWS  150000          // users then items, matching d_out layout
#define NNZ_C   1600000
#define DIM     64

#define CHUNK   1024
#define NBLK    147             // ceil(150000 / 1024)

#define NB_U    1563            // ceil(100000/64) user-gemm blocks
#define NB_I    782             // ceil(50000/64)  item-gemm blocks
#define NB_H    1024            // histogram blocks

// ---- device scratch (no-alloc rule) ----
__device__ __half g_xw_user[(size_t)N_USERS * DIM];   // 12.8 MB
__device__ __half g_xw_item[(size_t)N_ITEMS * DIM];   //  6.4 MB
__device__ int    g_cnt[N_ROWS];
__device__ int    g_off[N_ROWS + 1];
__device__ int    g_cur[N_ROWS];
__device__ int2   g_perm[2 * NNZ_C];                  // 25.6 MB: (src_idx, val-bits)

// ---------------------------------------------------------------------------
// Fused kernel:
//   blocks [0, NB_U)             : user GEMM tile  (Y = user_x @ user_w -> fp16)
//   blocks [NB_U, NB_U+NB_I)     : item GEMM tile
//   blocks [NB_U+NB_I, +NB_H)    : degree histogram over combined row space
// All three parts are independent; fusing overlaps atomic-bound hist with
// FMA-bound GEMM and removes two launch boundaries.
// ---------------------------------------------------------------------------
__global__ __launch_bounds__(256) void fused_gemm_hist_kernel(
    const float* __restrict__ user_x, const float* __restrict__ user_w,
    const float* __restrict__ item_x, const float* __restrict__ item_w,
    const int* __restrict__ rows, const int* __restrict__ cols)
{
    const int tid = threadIdx.x;
    const int b   = blockIdx.x;

    if (b >= NB_U + NB_I) {
        // ---- histogram part ----
        const int h = b - (NB_U + NB_I);
        for (int e = h * 256 + tid; e < NNZ_C; e += NB_H * 256) {
            atomicAdd(&g_cnt[rows[e]], 1);
            atomicAdd(&g_cnt[N_USERS + cols[e]], 1);
        }
        return;
    }

    // ---- GEMM part ----
    __shared__ float Ws[64 * 64];
    __shared__ float Xt[64 * 68];

    const bool   is_item = (b >= NB_U);
    const int    gb      = is_item ? (b - NB_U) : b;
    const int    nrows   = is_item ? N_ITEMS : N_USERS;
    const float* X       = is_item ? item_x : user_x;
    const float* W       = is_item ? item_w : user_w;
    __half*      Y       = is_item ? g_xw_item : g_xw_user;
    const int    row0    = gb * 64;

    {
        const float4* W4  = (const float4*)W;
        float4*       Ws4 = (float4*)Ws;
        #pragma unroll
        for (int i = 0; i < 4; i++) Ws4[tid + i * 256] = W4[tid + i * 256];
    }
    #pragma unroll
    for (int i = 0; i < 4; i++) {
        int idx = tid + i * 256;
        int r   = idx >> 4;
        int k4  = (idx & 15) * 4;
        float4 v = make_float4(0.f, 0.f, 0.f, 0.f);
        if (row0 + r < nrows)
            v = *(const float4*)(X + (size_t)(row0 + r) * DIM + k4);
        Xt[(k4 + 0) * 68 + r] = v.x;
        Xt[(k4 + 1) * 68 + r] = v.y;
        Xt[(k4 + 2) * 68 + r] = v.z;
        Xt[(k4 + 3) * 68 + r] = v.w;
    }
    __syncthreads();

    const int tx = tid & 15;
    const int ty = tid >> 4;

    float acc[4][4] = {};
    #pragma unroll 16
    for (int k = 0; k < 64; k++) {
        float4 a = *(const float4*)&Xt[k * 68 + ty * 4];
        float4 bq = *(const float4*)&Ws[k * 64 + tx * 4];
        float av[4] = {a.x, a.y, a.z, a.w};
        float bv[4] = {bq.x, bq.y, bq.z, bq.w};
        #pragma unroll
        for (int i = 0; i < 4; i++)
            #pragma unroll
            for (int j = 0; j < 4; j++)
                acc[i][j] += av[i] * bv[j];
    }

    #pragma unroll
    for (int i = 0; i < 4; i++) {
        int r = row0 + ty * 4 + i;
        if (r < nrows) {
            __half2* Yp = (__half2*)(Y + (size_t)r * DIM + tx * 4);
            Yp[0] = __floats2half2_rn(acc[i][0], acc[i][1]);
            Yp[1] = __floats2half2_rn(acc[i][2], acc[i][3]);
        }
    }
}

// ---------------------------------------------------------------------------
// Single-kernel exclusive scan: block b brute-force re-sums g_cnt[0, b*CHUNK)
// (43 MB total of L2 reads across 147 blocks -- ~4us, zero inter-block sync),
// then local-scans its CHUNK and writes both g_off and g_cur.
// ---------------------------------------------------------------------------
__global__ __launch_bounds__(256) void scan_kernel()
{
    __shared__ int red[8];
    __shared__ int warpsum[8];
    __shared__ int blockbase_sh;

    const int b = blockIdx.x, t = threadIdx.x;

    // phase 1: prefix base = sum of g_cnt[0 .. b*CHUNK)
    int s = 0;
    const int limit = b * CHUNK;
    #pragma unroll 4
    for (int i = t; i < limit; i += 256) s += g_cnt[i];
    #pragma unroll
    for (int o = 16; o > 0; o >>= 1) s += __shfl_down_sync(0xffffffffu, s, o);
    if ((t & 31) == 0) red[t >> 5] = s;
    __syncthreads();
    if (t < 8) {
        int v = red[t];
        #pragma unroll
        for (int o = 4; o > 0; o >>= 1) v += __shfl_down_sync(0xffu, v, o);
        if (t == 0) blockbase_sh = v;
    }
    __syncthreads();
    const int base = blockbase_sh;

    // phase 2: local exclusive scan of this block's CHUNK elements
    const int ebase = b * CHUNK + t * 4;
    int c[4]; int sl = 0;
    #pragma unroll
    for (int i = 0; i < 4; i++) {
        int idx = ebase + i;
        c[i] = (idx < N_ROWS) ? g_cnt[idx] : 0;
        sl += c[i];
    }
    const int lane = t & 31, w = t >> 5;
    int incl = sl;
    #pragma unroll
    for (int o = 1; o < 32; o <<= 1) {
        int x = __shfl_up_sync(0xffffffffu, incl, o);
        if (lane >= o) incl += x;
    }
    if (lane == 31) warpsum[w] = incl;
    __syncthreads();
    if (t < 8) {
        int v  = warpsum[t];
        int iv = v;
        #pragma unroll
        for (int o = 1; o < 8; o <<= 1) {
            int x = __shfl_up_sync(0xffu, iv, o);
            if (t >= o) iv += x;
        }
        warpsum[t] = iv - v;
    }
    __syncthreads();
    int excl = base + warpsum[w] + (incl - sl);
    #pragma unroll
    for (int i = 0; i < 4; i++) {
        int idx = ebase + i;
        if (idx < N_ROWS) {
            g_off[idx] = excl;
            g_cur[idx] = excl;
            excl += c[i];
        }
    }
    if (b == 0 && t == 0) g_off[N_ROWS] = 2 * NNZ_C;
}

// ---------------------------------------------------------------------------
// Permute edges into bucketed layout: (source row index, fp32 value bits)
// ---------------------------------------------------------------------------
__global__ __launch_bounds__(256) void permute_kernel(
    const int* __restrict__ rows, const int* __restrict__ cols,
    const float* __restrict__ vals)
{
    int e = blockIdx.x * blockDim.x + threadIdx.x;
    if (e >= NNZ_C) return;
    int   r = rows[e];
    int   c = cols[e];
    int   v = __float_as_int(vals[e]);
    int p0 = atomicAdd(&g_cur[r], 1);
    g_perm[p0] = make_int2(c, v);
    int p1 = atomicAdd(&g_cur[N_USERS + c], 1);
    g_perm[p1] = make_int2(r, v);
}

// ---------------------------------------------------------------------------
// SpMM gather: one warp per output row, fp16 sources, fp32 accumulation,
// fused ReLU. Each lane owns 2 output columns (one half2 load per edge).
// ---------------------------------------------------------------------------
__global__ __launch_bounds__(256) void spmm_gather_kernel(float* __restrict__ out)
{
    const int wid  = (blockIdx.x * blockDim.x + threadIdx.x) >> 5;
    const int lane = threadIdx.x & 31;
    if (wid >= N_ROWS) return;

    const int start = g_off[wid];
    const int end   = g_off[wid + 1];
    const __half* __restrict__ src = (wid < N_USERS) ? g_xw_item : g_xw_user;

    float a0 = 0.f, a1 = 0.f;
    for (int e = start; e < end; e += 32) {
        const int nedge = min(32, end - e);
        int2 p = make_int2(0, 0);
        if (lane < nedge) p = g_perm[e + lane];
        #pragma unroll 8
        for (int j = 0; j < nedge; j++) {
            int   idx = __shfl_sync(0xffffffffu, p.x, j);
            float v   = __int_as_float(__shfl_sync(0xffffffffu, p.y, j));
            __half2 h = __ldg((const __half2*)(src + (size_t)idx * DIM) + lane);
            float2  f = __half22float2(h);
            a0 += v * f.x;
            a1 += v * f.y;
        }
    }
    float2 o;
    o.x = fmaxf(a0, 0.f);
    o.y = fmaxf(a1, 0.f);
    *((float2*)(out + (size_t)wid * DIM) + lane) = o;
}

// ---------------------------------------------------------------------------
extern "C" void kernel_launch(void* const* d_in, const int* in_sizes, int n_in,
                              void* d_out, int out_size)
{
    const float* user_x  = (const float*)d_in[0];
    const float* item_x  = (const float*)d_in[1];
    const float* user_w  = (const float*)d_in[2];
    const float* item_w  = (const float*)d_in[3];
    const int*   ui_rows = (const int*)d_in[4];
    const int*   ui_cols = (const int*)d_in[5];
    const float* ui_vals = (const float*)d_in[6];

    float* out = (float*)d_out;

    void* p_cnt = nullptr;
    cudaGetSymbolAddress(&p_cnt, g_cnt);

    // node 0: zero degree counters
    cudaMemsetAsync(p_cnt, 0, N_ROWS * sizeof(int), 0);

    // node 1: both GEMMs + degree histogram, fused
    fused_gemm_hist_kernel<<<NB_U + NB_I + NB_H, 256>>>(
        user_x, user_w, item_x, item_w, ui_rows, ui_cols);

    // node 2: single-kernel exclusive scan (writes g_off AND g_cur)
    scan_kernel<<<NBLK, 256>>>();

    // node 3: bucket edges
    permute_kernel<<<(NNZ_C + 255) / 256, 256>>>(ui_rows, ui_cols, ui_vals);

    // node 4: gather SpMM with fused ReLU (writes every output row)
    spmm_gather_kernel<<<(N_ROWS * 32 + 255) / 256, 256>>>(out);
}